// round 11
// baseline (speedup 1.0000x reference)
#include <cuda_runtime.h>
#include <cstdint>

// Problem dims (fixed by the reference)
#define NROWS 32768
#define D_IN  512
#define D_HID 2048
#define D_OUT 512
#define KW1   (D_IN  / 32)   // 16 words
#define KW2   (D_HID / 32)   // 64 words

// ---------------------------------------------------------------------------
// Scratch (__device__ globals; no cudaMalloc allowed). Bit-packed sign data:
// bit = 1  <=>  value < 0   (so sign(0) -> +1 matches the reference).
// ---------------------------------------------------------------------------
__device__ __align__(256) uint32_t g_xb [NROWS * KW1];   // 2 MB
__device__ __align__(256) uint32_t g_h1b[NROWS * KW2];   // 8 MB
__device__ __align__(256) uint32_t g_h2b[NROWS * KW2];   // 8 MB
__device__ __align__(256) uint32_t g_w1b[D_HID * KW1];   // 128 KB
__device__ __align__(256) uint32_t g_w2b[D_HID * KW2];   // 512 KB
__device__ __align__(256) uint32_t g_w3b[D_OUT * KW2];   // 128 KB
__device__ float g_beta1[NROWS];
__device__ float g_beta2[NROWS];   // accumulates sum|h1| per row
__device__ float g_beta3[NROWS];   // accumulates sum|h2| per row
__device__ float g_alpha1[D_HID];
__device__ float g_alpha2[D_HID];
__device__ float g_alpha3[D_OUT];

// ---------------------------------------------------------------------------
// Helpers
// ---------------------------------------------------------------------------
__device__ __forceinline__ uint32_t smem_u32(const void* p) {
    uint32_t a;
    asm("{ .reg .u64 t; cvta.to.shared.u64 t, %1; cvt.u32.u64 %0, t; }"
        : "=r"(a) : "l"(p));
    return a;
}
__device__ __forceinline__ void cp_async16(uint32_t s, const void* g) {
    asm volatile("cp.async.ca.shared.global [%0], [%1], 16;" :: "r"(s), "l"(g));
}

// ---------------------------------------------------------------------------
// Core row-pack: float row -> sign bits + mean(|.|). One warp per row.
// ---------------------------------------------------------------------------
__device__ __forceinline__ void pack_row(const float* __restrict__ src,
                                         uint32_t* __restrict__ dst,
                                         float* __restrict__ scale,
                                         int row, int lane, int Kw, float inv) {
    const float* s = src + (size_t)row * (Kw << 5);
    float sum = 0.f;
    uint32_t w0 = 0, w1 = 0;
    for (int w = 0; w < Kw; ++w) {
        float v = s[w * 32 + lane];                       // coalesced 128B
        sum += fabsf(v);
        uint32_t b = __ballot_sync(0xffffffffu, v < 0.f);
        if (lane == (w & 31)) { if (w < 32) w0 = b; else w1 = b; }
    }
#pragma unroll
    for (int o = 16; o; o >>= 1) sum += __shfl_xor_sync(0xffffffffu, sum, o);
    if (lane < Kw)      dst[(size_t)row * Kw + lane]      = w0;
    if (lane + 32 < Kw) dst[(size_t)row * Kw + lane + 32] = w1;
    if (lane == 0) scale[row] = sum * inv;
}

// x pack (also zeroes the beta accumulators -> deterministic replays)
__global__ void pack_x(const float* __restrict__ src, uint32_t* __restrict__ dst,
                       float* __restrict__ scale,
                       float* __restrict__ z1, float* __restrict__ z2) {
    const int row  = (blockIdx.x * blockDim.x + threadIdx.x) >> 5;
    const int lane = threadIdx.x & 31;
    pack_row(src, dst, scale, row, lane, KW1, 1.f / D_IN);
    if (lane == 0) { z1[row] = 0.f; z2[row] = 0.f; }
}

// fused W1+W2+W3 pack: blocks [0,256) W1, [256,512) W2, [512,576) W3
__global__ void pack_w(const float* __restrict__ W1s, uint32_t* __restrict__ w1d, float* __restrict__ a1,
                       const float* __restrict__ W2s, uint32_t* __restrict__ w2d, float* __restrict__ a2,
                       const float* __restrict__ W3s, uint32_t* __restrict__ w3d, float* __restrict__ a3) {
    const int bx   = blockIdx.x;
    const int lane = threadIdx.x & 31;
    const int wrp  = threadIdx.x >> 5;
    if (bx < 256) {
        pack_row(W1s, w1d, a1, bx * 8 + wrp, lane, KW1, 1.f / D_IN);
    } else if (bx < 512) {
        pack_row(W2s, w2d, a2, (bx - 256) * 8 + wrp, lane, KW2, 1.f / D_HID);
    } else {
        pack_row(W3s, w3d, a3, (bx - 512) * 8 + wrp, lane, KW2, 1.f / D_HID);
    }
}

// ---------------------------------------------------------------------------
// Popcount binary GEMM.
//   dot[m][n] = K - 2 * sum_w popc(A[m][w] ^ B[n][w])
//   y = dot * beta[m]*beta_mul * alpha[n] + bias[n]
// SIGN_OUT=1: emit sign bits of y (== sign of prelu(y)) into the next layer's
//             bit matrix via ballots; accumulate sum|prelu(y)| per row.
// SIGN_OUT=0: write y as fp32.
//
// CTA tile 128x128, 256 threads, 8x8 outputs/thread. K fully smem-resident,
// padded row stride PW = KW+4 words (16B-aligned rows for LDS.128; B-frag
// lanes cover all 32 banks exactly once per 8-lane phase; A-frags broadcast).
// Inner step = 4 k-words via uint4 fragments; B processed in 4 groups of 2
// columns to bound live registers (~116 << 128 cap -> no spill risk).
// Thread map: tx = tid&15 (N), ty = tid>>4 (M).
//   rows  m0 + ty*8 + r   (r = 0..7)
//   cols  n0 + tx + 16*j  (j = 0..7)
// ---------------------------------------------------------------------------
template <int KW, int SIGN_OUT>
__global__ void __launch_bounds__(256, 2)
bin_gemm_pc(const uint32_t* __restrict__ A, const uint32_t* __restrict__ Bm,
            int Nout,
            const float* __restrict__ beta, float beta_mul,
            const float* __restrict__ alpha, const float* __restrict__ bias,
            const float* __restrict__ prelu_w,
            uint32_t* __restrict__ bOut, float* __restrict__ betaNext,
            float* __restrict__ fOut)
{
    constexpr int PW = KW + 4;                 // padded smem row stride (words)
    extern __shared__ uint32_t sh[];
    uint32_t* As = sh;                         // [128][PW]
    uint32_t* Bs = sh + 128 * PW;              // [128][PW]

    const int tid = threadIdx.x;
    const int tx  = tid & 15;
    const int ty  = tid >> 4;
    const int m0  = blockIdx.y * 128;
    const int n0  = blockIdx.x * 128;

    // ---- stage both tiles (K fully resident; 16B cp.async chunks) ----
    {
        const uint32_t asb = smem_u32(As), bsb = smem_u32(Bs);
        constexpr int CH = KW / 4;             // 16B chunks per row
#pragma unroll
        for (int i = 0; i < (128 * CH) / 256; ++i) {
            int idx = tid + i * 256;
            int r = idx / CH, c = idx % CH;
            cp_async16(asb + (r * PW + c * 4) * 4, A  + (size_t)(m0 + r) * KW + c * 4);
            cp_async16(bsb + (r * PW + c * 4) * 4, Bm + (size_t)(n0 + r) * KW + c * 4);
        }
        asm volatile("cp.async.commit_group;");
        asm volatile("cp.async.wait_group 0;");
    }
    __syncthreads();

    // ---- main loop: 8x8 register tile, 4 k-words per step (LDS.128) ----
    uint32_t acc[8][8];
#pragma unroll
    for (int i = 0; i < 8; ++i)
#pragma unroll
        for (int j = 0; j < 8; ++j) acc[i][j] = 0;

#pragma unroll 1
    for (int k = 0; k < KW; k += 4) {
        uint4 a4[8];
#pragma unroll
        for (int i = 0; i < 8; ++i)
            a4[i] = *(const uint4*)&As[(ty * 8 + i) * PW + k];
#pragma unroll
        for (int jg = 0; jg < 4; ++jg) {
            uint4 b4[2];
#pragma unroll
            for (int j2 = 0; j2 < 2; ++j2)
                b4[j2] = *(const uint4*)&Bs[(tx + 16 * (jg * 2 + j2)) * PW + k];
#pragma unroll
            for (int i = 0; i < 8; ++i)
#pragma unroll
                for (int j2 = 0; j2 < 2; ++j2)
                    acc[i][jg * 2 + j2] +=
                        (__popc(a4[i].x ^ b4[j2].x) + __popc(a4[i].y ^ b4[j2].y)) +
                        (__popc(a4[i].z ^ b4[j2].z) + __popc(a4[i].w ^ b4[j2].w));
        }
    }

    // ---- epilogue ----
    const float Kf = (float)(KW * 32);
    float al[8], bi[8];
#pragma unroll
    for (int j = 0; j < 8; ++j) {
        al[j] = alpha[n0 + tx + 16 * j];
        bi[j] = bias [n0 + tx + 16 * j];
    }
    const int sh16 = tid & 16;                 // lane>=16 picks high half of ballots

    if (SIGN_OUT) {
        const float pw = prelu_w[0];
#pragma unroll 1
        for (int r = 0; r < 8; ++r) {
            const int row = m0 + ty * 8 + r;
            const float bm = beta[row] * beta_mul;
            float yv[8];
            uint32_t bal[8];
            float asum = 0.f;
#pragma unroll
            for (int j = 0; j < 8; ++j)
                yv[j] = fmaf((Kf - 2.f * (float)acc[r][j]) * bm, al[j], bi[j]);
#pragma unroll
            for (int j = 0; j < 8; ++j)
                bal[j] = __ballot_sync(0xffffffffu, yv[j] < 0.f);
#pragma unroll
            for (int j = 0; j < 8; ++j) {
                float h = yv[j] > 0.f ? yv[j] : pw * yv[j];
                asum += fabsf(h);
            }
            if (tx == 0) {                     // lanes 0 & 16: one row each
#pragma unroll
                for (int w = 0; w < 4; ++w) {
                    uint32_t word = ((bal[2 * w]      >> sh16) & 0xFFFFu) |
                                    (((bal[2 * w + 1] >> sh16) & 0xFFFFu) << 16);
                    bOut[(size_t)row * (Nout >> 5) + (n0 >> 5) + w] = word;
                }
            }
#pragma unroll
            for (int o = 1; o < 16; o <<= 1)
                asum += __shfl_xor_sync(0xffffffffu, asum, o);
            if (tx == 0) atomicAdd(&betaNext[row], asum);
        }
    } else {
#pragma unroll 1
        for (int r = 0; r < 8; ++r) {
            const int row = m0 + ty * 8 + r;
            const float bm = beta[row] * beta_mul;
            float* o = fOut + (size_t)row * Nout + n0 + tx;
#pragma unroll
            for (int j = 0; j < 8; ++j)
                o[16 * j] = fmaf((Kf - 2.f * (float)acc[r][j]) * bm, al[j], bi[j]);
        }
    }
}

// ---------------------------------------------------------------------------
// Launch: packW(0) -> packX(1) -> gemm1(2) -> gemm2(3) -> gemm3(4)
// (gemm2 deliberately at launch index 3: that's the slot ncu captures)
// ---------------------------------------------------------------------------
extern "C" void kernel_launch(void* const* d_in, const int* in_sizes, int n_in,
                              void* d_out, int out_size) {
    const float* x  = (const float*)d_in[0];
    const float* W1 = (const float*)d_in[1];
    const float* b1 = (const float*)d_in[2];
    const float* W2 = (const float*)d_in[3];
    const float* b2 = (const float*)d_in[4];
    const float* W3 = (const float*)d_in[5];
    const float* b3 = (const float*)d_in[6];
    const float* pw = (const float*)d_in[7];
    float* out = (float*)d_out;

    void *xb, *h1, *h2, *w1, *w2, *w3, *be1, *be2, *be3, *al1, *al2, *al3;
    cudaGetSymbolAddress(&xb,  g_xb);
    cudaGetSymbolAddress(&h1,  g_h1b);
    cudaGetSymbolAddress(&h2,  g_h2b);
    cudaGetSymbolAddress(&w1,  g_w1b);
    cudaGetSymbolAddress(&w2,  g_w2b);
    cudaGetSymbolAddress(&w3,  g_w3b);
    cudaGetSymbolAddress(&be1, g_beta1);
    cudaGetSymbolAddress(&be2, g_beta2);
    cudaGetSymbolAddress(&be3, g_beta3);
    cudaGetSymbolAddress(&al1, g_alpha1);
    cudaGetSymbolAddress(&al2, g_alpha2);
    cudaGetSymbolAddress(&al3, g_alpha3);

    const int smem1 = 2 * 128 * (KW1 + 4) * 4;   // 20480 B
    const int smem2 = 2 * 128 * (KW2 + 4) * 4;   // 69632 B
    cudaFuncSetAttribute(bin_gemm_pc<KW1, 1>, cudaFuncAttributeMaxDynamicSharedMemorySize, smem1);
    cudaFuncSetAttribute(bin_gemm_pc<KW2, 1>, cudaFuncAttributeMaxDynamicSharedMemorySize, smem2);
    cudaFuncSetAttribute(bin_gemm_pc<KW2, 0>, cudaFuncAttributeMaxDynamicSharedMemorySize, smem2);

    // launch 0: fused weight packs (W1: 256 blocks, W2: 256, W3: 64)
    pack_w<<<576, 256>>>(W1, (uint32_t*)w1, (float*)al1,
                         W2, (uint32_t*)w2, (float*)al2,
                         W3, (uint32_t*)w3, (float*)al3);
    // launch 1: x pack (+ beta2/beta3 zeroing)
    pack_x<<<NROWS / 8, 256>>>(x, (uint32_t*)xb, (float*)be1,
                               (float*)be2, (float*)be3);

    dim3 blk(256);
    dim3 g12(D_HID / 128, NROWS / 128);   // (16, 256)
    dim3 g3 (D_OUT / 128, NROWS / 128);   // (4, 256)

    // launch 2 — layer 1: A = sign(x) bits [K=512], beta1 already the mean
    bin_gemm_pc<KW1, 1><<<g12, blk, smem1>>>((const uint32_t*)xb, (const uint32_t*)w1,
        D_HID, (const float*)be1, 1.f, (const float*)al1, b1, pw,
        (uint32_t*)h1, (float*)be2, nullptr);

    // launch 3 — layer 2 (profiled slot): beta2 = sum|h1| -> mean via 1/2048
    bin_gemm_pc<KW2, 1><<<g12, blk, smem2>>>((const uint32_t*)h1, (const uint32_t*)w2,
        D_HID, (const float*)be2, 1.f / D_HID, (const float*)al2, b2, pw,
        (uint32_t*)h2, (float*)be3, nullptr);

    // launch 4 — layer 3: fp32 output
    bin_gemm_pc<KW2, 0><<<g3, blk, smem2>>>((const uint32_t*)h2, (const uint32_t*)w3,
        D_OUT, (const float*)be3, 1.f / D_HID, (const float*)al3, b3, pw,
        nullptr, nullptr, out);
}

// round 14
// speedup vs baseline: 1.2795x; 1.2795x over previous
#include <cuda_runtime.h>
#include <cstdint>

// Problem dims (fixed by the reference)
#define NROWS 32768
#define D_IN  512
#define D_HID 2048
#define D_OUT 512
#define KW1   (D_IN  / 32)   // 16 words
#define KW2   (D_HID / 32)   // 64 words

// ---------------------------------------------------------------------------
// Scratch (__device__ globals; no cudaMalloc allowed). Bit-packed sign data:
// bit = 1  <=>  value < 0   (so sign(0) -> +1 matches the reference).
// ---------------------------------------------------------------------------
__device__ __align__(256) uint32_t g_xb [NROWS * KW1];   // 2 MB
__device__ __align__(256) uint32_t g_h1b[NROWS * KW2];   // 8 MB
__device__ __align__(256) uint32_t g_h2b[NROWS * KW2];   // 8 MB
__device__ __align__(256) uint32_t g_w1b[D_HID * KW1];   // 128 KB
__device__ __align__(256) uint32_t g_w2b[D_HID * KW2];   // 512 KB
__device__ __align__(256) uint32_t g_w3b[D_OUT * KW2];   // 128 KB
__device__ float g_beta1[NROWS];
__device__ float g_beta2[NROWS];   // accumulates sum|h1| per row
__device__ float g_beta3[NROWS];   // accumulates sum|h2| per row
__device__ float g_alpha1[D_HID];
__device__ float g_alpha2[D_HID];
__device__ float g_alpha3[D_OUT];

// ---------------------------------------------------------------------------
// Helpers
// ---------------------------------------------------------------------------
__device__ __forceinline__ uint32_t smem_u32(const void* p) {
    uint32_t a;
    asm("{ .reg .u64 t; cvta.to.shared.u64 t, %1; cvt.u32.u64 %0, t; }"
        : "=r"(a) : "l"(p));
    return a;
}
__device__ __forceinline__ void cp_async16(uint32_t s, const void* g) {
    asm volatile("cp.async.ca.shared.global [%0], [%1], 16;" :: "r"(s), "l"(g));
}

// Guaranteed single-instruction 3-input logic (no reliance on ptxas fusion).
__device__ __forceinline__ uint32_t lop3_xor3(uint32_t a, uint32_t b, uint32_t c) {
    uint32_t r;
    asm("lop3.b32 %0, %1, %2, %3, 0x96;" : "=r"(r) : "r"(a), "r"(b), "r"(c));
    return r;   // a ^ b ^ c
}
__device__ __forceinline__ uint32_t lop3_maj(uint32_t a, uint32_t b, uint32_t c) {
    uint32_t r;
    asm("lop3.b32 %0, %1, %2, %3, 0xE8;" : "=r"(r) : "r"(a), "r"(b), "r"(c));
    return r;   // majority(a,b,c)
}

// CSA-compressed popcount accumulate over a 4-word XOR chunk.
// x0+x1+x2 = s1 + 2*maj(x0,x1,x2); s1+x3 = s2 + 2*c2
//   => sum popc = popc(s2) + 2*(popc(c1) + popc(c2))
// 3 POPC (slow pipe, rt~8) instead of 4; sum/majority are explicit LOP3s.
__device__ __forceinline__ void acc_csa4(uint32_t& acc, uint4 a, uint4 b) {
    const uint32_t x0 = a.x ^ b.x, x1 = a.y ^ b.y;
    const uint32_t x2 = a.z ^ b.z, x3 = a.w ^ b.w;
    const uint32_t s1 = lop3_xor3(x0, x1, x2);
    const uint32_t c1 = lop3_maj (x0, x1, x2);
    const uint32_t s2 = s1 ^ x3;
    const uint32_t c2 = s1 & x3;
    acc += __popc(s2) + 2u * (__popc(c1) + __popc(c2));
}

// ---------------------------------------------------------------------------
// Core row-pack: float row -> sign bits + mean(|.|). One warp per row.
// ---------------------------------------------------------------------------
__device__ __forceinline__ void pack_row(const float* __restrict__ src,
                                         uint32_t* __restrict__ dst,
                                         float* __restrict__ scale,
                                         int row, int lane, int Kw, float inv) {
    const float* s = src + (size_t)row * (Kw << 5);
    float sum = 0.f;
    uint32_t w0 = 0, w1 = 0;
    for (int w = 0; w < Kw; ++w) {
        float v = s[w * 32 + lane];                       // coalesced 128B
        sum += fabsf(v);
        uint32_t b = __ballot_sync(0xffffffffu, v < 0.f);
        if (lane == (w & 31)) { if (w < 32) w0 = b; else w1 = b; }
    }
#pragma unroll
    for (int o = 16; o; o >>= 1) sum += __shfl_xor_sync(0xffffffffu, sum, o);
    if (lane < Kw)      dst[(size_t)row * Kw + lane]      = w0;
    if (lane + 32 < Kw) dst[(size_t)row * Kw + lane + 32] = w1;
    if (lane == 0) scale[row] = sum * inv;
}

// x pack (also zeroes the beta accumulators -> deterministic replays)
__global__ void pack_x(const float* __restrict__ src, uint32_t* __restrict__ dst,
                       float* __restrict__ scale,
                       float* __restrict__ z1, float* __restrict__ z2) {
    const int row  = (blockIdx.x * blockDim.x + threadIdx.x) >> 5;
    const int lane = threadIdx.x & 31;
    pack_row(src, dst, scale, row, lane, KW1, 1.f / D_IN);
    if (lane == 0) { z1[row] = 0.f; z2[row] = 0.f; }
}

// fused W1+W2+W3 pack: blocks [0,256) W1, [256,512) W2, [512,576) W3
__global__ void pack_w(const float* __restrict__ W1s, uint32_t* __restrict__ w1d, float* __restrict__ a1,
                       const float* __restrict__ W2s, uint32_t* __restrict__ w2d, float* __restrict__ a2,
                       const float* __restrict__ W3s, uint32_t* __restrict__ w3d, float* __restrict__ a3) {
    const int bx   = blockIdx.x;
    const int lane = threadIdx.x & 31;
    const int wrp  = threadIdx.x >> 5;
    if (bx < 256) {
        pack_row(W1s, w1d, a1, bx * 8 + wrp, lane, KW1, 1.f / D_IN);
    } else if (bx < 512) {
        pack_row(W2s, w2d, a2, (bx - 256) * 8 + wrp, lane, KW2, 1.f / D_HID);
    } else {
        pack_row(W3s, w3d, a3, (bx - 512) * 8 + wrp, lane, KW2, 1.f / D_HID);
    }
}

// ---------------------------------------------------------------------------
// Popcount binary GEMM (CSA-compressed inner loop).
//   dot[m][n] = K - 2 * sum_w popc(A[m][w] ^ B[n][w])
//   y = dot * beta[m]*beta_mul * alpha[n] + bias[n]
// SIGN_OUT=1: emit sign bits of y (== sign of prelu(y)) into the next layer's
//             bit matrix via ballots; accumulate sum|prelu(y)| per row.
// SIGN_OUT=0: write y as fp32.
//
// CTA tile 128x128, 256 threads, 8x8 outputs/thread. K fully smem-resident,
// padded row stride PW = KW+4 words (16B-aligned rows for LDS.128; B-frag
// lanes cover all 32 banks exactly once per 8-lane phase; A-frags broadcast).
// Inner step = 4 k-words via uint4 fragments + stateless CSA popcount
// (3 POPC / 4 words instead of 4 -> rebalances the slow POPC pipe vs LOP3).
// Thread map: tx = tid&15 (N), ty = tid>>4 (M).
//   rows  m0 + ty*8 + r   (r = 0..7)
//   cols  n0 + tx + 16*j  (j = 0..7)
// ---------------------------------------------------------------------------
template <int KW, int SIGN_OUT>
__global__ void __launch_bounds__(256, 2)
bin_gemm_pc(const uint32_t* __restrict__ A, const uint32_t* __restrict__ Bm,
            int Nout,
            const float* __restrict__ beta, float beta_mul,
            const float* __restrict__ alpha, const float* __restrict__ bias,
            const float* __restrict__ prelu_w,
            uint32_t* __restrict__ bOut, float* __restrict__ betaNext,
            float* __restrict__ fOut)
{
    constexpr int PW = KW + 4;                 // padded smem row stride (words)
    extern __shared__ uint32_t sh[];
    uint32_t* As = sh;                         // [128][PW]
    uint32_t* Bs = sh + 128 * PW;              // [128][PW]

    const int tid = threadIdx.x;
    const int tx  = tid & 15;
    const int ty  = tid >> 4;
    const int m0  = blockIdx.y * 128;
    const int n0  = blockIdx.x * 128;

    // ---- stage both tiles (K fully resident; 16B cp.async chunks) ----
    {
        const uint32_t asb = smem_u32(As), bsb = smem_u32(Bs);
        constexpr int CH = KW / 4;             // 16B chunks per row
#pragma unroll
        for (int i = 0; i < (128 * CH) / 256; ++i) {
            int idx = tid + i * 256;
            int r = idx / CH, c = idx % CH;
            cp_async16(asb + (r * PW + c * 4) * 4, A  + (size_t)(m0 + r) * KW + c * 4);
            cp_async16(bsb + (r * PW + c * 4) * 4, Bm + (size_t)(n0 + r) * KW + c * 4);
        }
        asm volatile("cp.async.commit_group;");
        asm volatile("cp.async.wait_group 0;");
    }
    __syncthreads();

    // ---- main loop: 8x8 register tile, 4 k-words per step (LDS.128) ----
    uint32_t acc[8][8];
#pragma unroll
    for (int i = 0; i < 8; ++i)
#pragma unroll
        for (int j = 0; j < 8; ++j) acc[i][j] = 0;

#pragma unroll 1
    for (int k = 0; k < KW; k += 4) {
        uint4 a4[8];
#pragma unroll
        for (int i = 0; i < 8; ++i)
            a4[i] = *(const uint4*)&As[(ty * 8 + i) * PW + k];
#pragma unroll
        for (int jg = 0; jg < 4; ++jg) {
            uint4 b4[2];
#pragma unroll
            for (int j2 = 0; j2 < 2; ++j2)
                b4[j2] = *(const uint4*)&Bs[(tx + 16 * (jg * 2 + j2)) * PW + k];
#pragma unroll
            for (int i = 0; i < 8; ++i)
#pragma unroll
                for (int j2 = 0; j2 < 2; ++j2)
                    acc_csa4(acc[i][jg * 2 + j2], a4[i], b4[j2]);
        }
    }

    // ---- epilogue ----
    const float Kf = (float)(KW * 32);
    float al[8], bi[8];
#pragma unroll
    for (int j = 0; j < 8; ++j) {
        al[j] = alpha[n0 + tx + 16 * j];
        bi[j] = bias [n0 + tx + 16 * j];
    }
    const int sh16 = tid & 16;                 // lane>=16 picks high half of ballots

    if (SIGN_OUT) {
        const float pw = prelu_w[0];
#pragma unroll 1
        for (int r = 0; r < 8; ++r) {
            const int row = m0 + ty * 8 + r;
            const float bm = beta[row] * beta_mul;
            float yv[8];
            uint32_t bal[8];
            float asum = 0.f;
#pragma unroll
            for (int j = 0; j < 8; ++j)
                yv[j] = fmaf((Kf - 2.f * (float)acc[r][j]) * bm, al[j], bi[j]);
#pragma unroll
            for (int j = 0; j < 8; ++j)
                bal[j] = __ballot_sync(0xffffffffu, yv[j] < 0.f);
#pragma unroll
            for (int j = 0; j < 8; ++j) {
                float h = yv[j] > 0.f ? yv[j] : pw * yv[j];
                asum += fabsf(h);
            }
            if (tx == 0) {                     // lanes 0 & 16: one row each
#pragma unroll
                for (int w = 0; w < 4; ++w) {
                    uint32_t word = ((bal[2 * w]      >> sh16) & 0xFFFFu) |
                                    (((bal[2 * w + 1] >> sh16) & 0xFFFFu) << 16);
                    bOut[(size_t)row * (Nout >> 5) + (n0 >> 5) + w] = word;
                }
            }
#pragma unroll
            for (int o = 1; o < 16; o <<= 1)
                asum += __shfl_xor_sync(0xffffffffu, asum, o);
            if (tx == 0) atomicAdd(&betaNext[row], asum);
        }
    } else {
#pragma unroll 1
        for (int r = 0; r < 8; ++r) {
            const int row = m0 + ty * 8 + r;
            const float bm = beta[row] * beta_mul;
            float* o = fOut + (size_t)row * Nout + n0 + tx;
#pragma unroll
            for (int j = 0; j < 8; ++j)
                o[16 * j] = fmaf((Kf - 2.f * (float)acc[r][j]) * bm, al[j], bi[j]);
        }
    }
}

// ---------------------------------------------------------------------------
// Launch: packW(0) -> packX(1) -> gemm1(2) -> gemm2(3) -> gemm3(4)
// (gemm2 deliberately at launch index 3: that's the slot ncu captures)
// ---------------------------------------------------------------------------
extern "C" void kernel_launch(void* const* d_in, const int* in_sizes, int n_in,
                              void* d_out, int out_size) {
    const float* x  = (const float*)d_in[0];
    const float* W1 = (const float*)d_in[1];
    const float* b1 = (const float*)d_in[2];
    const float* W2 = (const float*)d_in[3];
    const float* b2 = (const float*)d_in[4];
    const float* W3 = (const float*)d_in[5];
    const float* b3 = (const float*)d_in[6];
    const float* pw = (const float*)d_in[7];
    float* out = (float*)d_out;

    void *xb, *h1, *h2, *w1, *w2, *w3, *be1, *be2, *be3, *al1, *al2, *al3;
    cudaGetSymbolAddress(&xb,  g_xb);
    cudaGetSymbolAddress(&h1,  g_h1b);
    cudaGetSymbolAddress(&h2,  g_h2b);
    cudaGetSymbolAddress(&w1,  g_w1b);
    cudaGetSymbolAddress(&w2,  g_w2b);
    cudaGetSymbolAddress(&w3,  g_w3b);
    cudaGetSymbolAddress(&be1, g_beta1);
    cudaGetSymbolAddress(&be2, g_beta2);
    cudaGetSymbolAddress(&be3, g_beta3);
    cudaGetSymbolAddress(&al1, g_alpha1);
    cudaGetSymbolAddress(&al2, g_alpha2);
    cudaGetSymbolAddress(&al3, g_alpha3);

    const int smem1 = 2 * 128 * (KW1 + 4) * 4;   // 20480 B
    const int smem2 = 2 * 128 * (KW2 + 4) * 4;   // 69632 B
    cudaFuncSetAttribute(bin_gemm_pc<KW1, 1>, cudaFuncAttributeMaxDynamicSharedMemorySize, smem1);
    cudaFuncSetAttribute(bin_gemm_pc<KW2, 1>, cudaFuncAttributeMaxDynamicSharedMemorySize, smem2);
    cudaFuncSetAttribute(bin_gemm_pc<KW2, 0>, cudaFuncAttributeMaxDynamicSharedMemorySize, smem2);

    // launch 0: fused weight packs (W1: 256 blocks, W2: 256, W3: 64)
    pack_w<<<576, 256>>>(W1, (uint32_t*)w1, (float*)al1,
                         W2, (uint32_t*)w2, (float*)al2,
                         W3, (uint32_t*)w3, (float*)al3);
    // launch 1: x pack (+ beta2/beta3 zeroing)
    pack_x<<<NROWS / 8, 256>>>(x, (uint32_t*)xb, (float*)be1,
                               (float*)be2, (float*)be3);

    dim3 blk(256);
    dim3 g12(D_HID / 128, NROWS / 128);   // (16, 256)
    dim3 g3 (D_OUT / 128, NROWS / 128);   // (4, 256)

    // launch 2 — layer 1: A = sign(x) bits [K=512], beta1 already the mean
    bin_gemm_pc<KW1, 1><<<g12, blk, smem1>>>((const uint32_t*)xb, (const uint32_t*)w1,
        D_HID, (const float*)be1, 1.f, (const float*)al1, b1, pw,
        (uint32_t*)h1, (float*)be2, nullptr);

    // launch 3 — layer 2 (profiled slot): beta2 = sum|h1| -> mean via 1/2048
    bin_gemm_pc<KW2, 1><<<g12, blk, smem2>>>((const uint32_t*)h1, (const uint32_t*)w2,
        D_HID, (const float*)be2, 1.f / D_HID, (const float*)al2, b2, pw,
        (uint32_t*)h2, (float*)be3, nullptr);

    // launch 4 — layer 3: fp32 output
    bin_gemm_pc<KW2, 0><<<g3, blk, smem2>>>((const uint32_t*)h2, (const uint32_t*)w3,
        D_OUT, (const float*)be3, 1.f / D_HID, (const float*)al3, b3, pw,
        nullptr, nullptr, out);
}